// round 4
// baseline (speedup 1.0000x reference)
#include <cuda_runtime.h>

#define G_TOTAL 32768
#define H1      150
#define PP      8

using u64 = unsigned long long;

// ---- packed f32x2 helpers (Blackwell sm_103a) ------------------------------
__device__ __forceinline__ u64 pk2(float a, float b) {
    u64 r;
    asm("mov.b64 %0,{%1,%2};" : "=l"(r)
        : "r"(__float_as_uint(a)), "r"(__float_as_uint(b)));
    return r;
}
__device__ __forceinline__ float2 upk2(u64 v) {
    unsigned lo, hi;
    asm("mov.b64 {%0,%1},%2;" : "=r"(lo), "=r"(hi) : "l"(v));
    return make_float2(__uint_as_float(lo), __uint_as_float(hi));
}
__device__ __forceinline__ u64 fma2(u64 a, u64 b, u64 c) {
    u64 d;
    asm("fma.rn.f32x2 %0,%1,%2,%3;" : "=l"(d) : "l"(a), "l"(b), "l"(c));
    return d;
}

// ---- constant-memory weights (uniform LDCU port, NOT the smem crossbar) ----
// W1c: [150][20] dup pairs {w,w}, k-major in row (18 used, 2 pad), 16B-aligned
// W2c: [150][8]  dup pairs {w,w}
// bc : b1 at [0..149], b2 at [152..159]
__constant__ u64   W1c[H1 * 20];
__constant__ u64   W2c[H1 * 8];
__constant__ float bc[160];

// __device__ scratch staged by prep kernel, then memcpy'd into const symbols
__device__ u64   scr_w1[H1 * 20];
__device__ u64   scr_w2[H1 * 8];
__device__ float scr_b[160];

__global__ void prep_kernel(const float* __restrict__ W1,
                            const float* __restrict__ W2,
                            const float* __restrict__ b1,
                            const float* __restrict__ b2)
{
    int i = blockIdx.x * 256 + threadIdx.x;
    if (i < H1 * 20) {
        int j = i / 20, k = i - j * 20;
        u64 v = 0ull;
        if (k < 18) {
            float w = W1[k * H1 + j];
            v = pk2(w, w);
        }
        scr_w1[i] = v;
    }
    if (i < H1 * 8) {
        float w = W2[i];
        scr_w2[i] = pk2(w, w);
    }
    if (i < 160) {
        float v = 0.0f;
        if (i < H1) v = b1[i];
        else if (i >= 152) v = b2[i - 152];
        scr_b[i] = v;
    }
}

// ---- shared memory: only the lane-distinct tail arrays ----------------------
#define SM_W3T 0
#define SM_B3  6000
#define SM_W4  6152
#define SM_FLOATS 6304
#define SM_BYTES  (SM_FLOATS * 4)

// ---- per-group tail: warp stats over 32 lanes + group MLP (verified code) ---
__device__ __noinline__ float group_tail(const float* a,
                                         const float* __restrict__ W3t,
                                         const float* __restrict__ b3s,
                                         const float* __restrict__ W4s,
                                         float b4v, int lane)
{
    u64 ag[20];   // packed agg pairs: ag[stat*4 + p/2] = {agg_p, agg_p+1}

    #pragma unroll
    for (int ph = 0; ph < 4; ++ph) {
        float va = a[2 * ph], vb = a[2 * ph + 1];

        // mean
        float sa = va, sb = vb;
        #pragma unroll
        for (int o = 16; o; o >>= 1) {
            sa += __shfl_xor_sync(0xffffffffu, sa, o);
            sb += __shfl_xor_sync(0xffffffffu, sb, o);
        }
        float meana = sa * (1.0f / 32.0f), meanb = sb * (1.0f / 32.0f);

        // unbiased variance (two-pass)
        float da = va - meana, db = vb - meanb;
        float qa = da * da, qb = db * db;
        #pragma unroll
        for (int o = 16; o; o >>= 1) {
            qa += __shfl_xor_sync(0xffffffffu, qa, o);
            qb += __shfl_xor_sync(0xffffffffu, qb, o);
        }
        float vara = qa * (1.0f / 31.0f), varb = qb * (1.0f / 31.0f);

        // min / max
        float mna = va, mxa = va, mnb = vb, mxb = vb;
        #pragma unroll
        for (int o = 16; o; o >>= 1) {
            mna = fminf(mna, __shfl_xor_sync(0xffffffffu, mna, o));
            mxa = fmaxf(mxa, __shfl_xor_sync(0xffffffffu, mxa, o));
            mnb = fminf(mnb, __shfl_xor_sync(0xffffffffu, mnb, o));
            mxb = fmaxf(mxb, __shfl_xor_sync(0xffffffffu, mxb, o));
        }

        // lower median via warp bitonic sort (two sorts interleaved)
        float ta = va, tb = vb;
        #pragma unroll
        for (int k = 2; k <= 32; k <<= 1) {
            #pragma unroll
            for (int j = k >> 1; j > 0; j >>= 1) {
                float oa = __shfl_xor_sync(0xffffffffu, ta, j);
                float ob = __shfl_xor_sync(0xffffffffu, tb, j);
                bool keep_lo = (((lane & j) == 0) == ((lane & k) == 0));
                float la = fminf(ta, oa), ha = fmaxf(ta, oa);
                float lb = fminf(tb, ob), hb = fmaxf(tb, ob);
                ta = keep_lo ? la : ha;
                tb = keep_lo ? lb : hb;
            }
        }
        float meda = __shfl_sync(0xffffffffu, ta, 15);
        float medb = __shfl_sync(0xffffffffu, tb, 15);

        ag[0 * 4 + ph] = pk2(meana, meanb);
        ag[1 * 4 + ph] = pk2(vara, varb);
        ag[2 * 4 + ph] = pk2(mna, mnb);
        ag[3 * 4 + ph] = pk2(meda, medb);
        ag[4 * 4 + ph] = pk2(mxa, mxb);
    }

    // group MLP: 40 -> 150 (relu) -> 1, hidden units strided over lanes
    // (W3t rows are lane-distinct -> efficient 128B/cyc crossbar use)
    float zp = 0.0f;
    #pragma unroll 1
    for (int j = lane; j < H1; j += 32) {
        const ulonglong2* wr = (const ulonglong2*)(W3t + j * 40);
        u64 t2a = 0ull, t2b = 0ull;
        #pragma unroll
        for (int q = 0; q < 10; ++q) {
            ulonglong2 w = wr[q];
            t2a = fma2(ag[2 * q],     w.x, t2a);
            t2b = fma2(ag[2 * q + 1], w.y, t2b);
        }
        float2 sa = upk2(t2a), sb = upk2(t2b);
        float t = (sa.x + sa.y) + (sb.x + sb.y) + b3s[j];
        t = fmaxf(t, 0.0f);
        zp = fmaf(t, W4s[j], zp);
    }
    #pragma unroll
    for (int o = 16; o; o >>= 1) zp += __shfl_xor_sync(0xffffffffu, zp, o);

    return 1.0f / (1.0f + __expf(-(zp + b4v)));
}

__global__ void __launch_bounds__(256, 2)
minn_fused_const_kernel(const float* __restrict__ x,
                        const int*   __restrict__ kmer,
                        const int*   __restrict__ indices,
                        const float* __restrict__ emb,
                        const float* __restrict__ W3, const float* __restrict__ b3,
                        const float* __restrict__ W4, const float* __restrict__ b4,
                        float* __restrict__ out)
{
    extern __shared__ float sm[];
    float* W3t = sm + SM_W3T;
    float* b3s = sm + SM_B3;
    float* W4s = sm + SM_W4;

    const int tid = threadIdx.x;

    for (int i = tid; i < 40 * H1; i += 256) {
        int j = i / 40, k = i - j * 40;
        W3t[i] = W3[k * H1 + j];
    }
    for (int i = tid; i < H1; i += 256) {
        b3s[i] = b3[i];
        W4s[i] = W4[i];
    }
    const float b4v = __ldg(b4);
    __syncthreads();

    const int warp = tid >> 5;
    const int lane = tid & 31;
    const int g0 = (blockIdx.x * 8 + warp) * 2;   // 2 groups per warp

    // ---- gather the 2 reads this lane owns as one packed f32x2 stream ----
    const int r0 = indices[(g0 + 0) * 32 + lane];
    const int r1 = indices[(g0 + 1) * 32 + lane];

    u64 in[18];   // {read of group g0, read of group g0+1}
    {
        const float4* p0 = (const float4*)(x + (size_t)r0 * 16);
        const float4* p1 = (const float4*)(x + (size_t)r1 * 16);
        #pragma unroll
        for (int q = 0; q < 4; ++q) {
            float4 v0 = p0[q], v1 = p1[q];
            in[4 * q + 0] = pk2(v0.x, v1.x);
            in[4 * q + 1] = pk2(v0.y, v1.y);
            in[4 * q + 2] = pk2(v0.z, v1.z);
            in[4 * q + 3] = pk2(v0.w, v1.w);
        }
        float2 e0 = ((const float2*)emb)[kmer[r0]];
        float2 e1 = ((const float2*)emb)[kmer[r1]];
        in[16] = pk2(e0.x, e1.x);
        in[17] = pk2(e0.y, e1.y);
    }

    // ---- per-read MLP 18->150(relu)->8(relu); weights via uniform const ----
    u64 acc[PP];
    #pragma unroll
    for (int p = 0; p < PP; ++p) {
        float bp = bc[152 + p];
        acc[p] = pk2(bp, bp);
    }

    #pragma unroll 2
    for (int j = 0; j < H1; ++j) {
        float bj = bc[j];
        // two independent accumulation chains for ILP
        u64 h0 = pk2(bj, bj), h1 = 0ull;
        const u64* w1r = W1c + j * 20;    // warp-uniform address -> LDCU
        #pragma unroll
        for (int q = 0; q < 9; ++q) {
            h0 = fma2(in[2 * q],     w1r[2 * q],     h0);
            h1 = fma2(in[2 * q + 1], w1r[2 * q + 1], h1);
        }
        float2 r0v = upk2(h0), r1v = upk2(h1);
        float hx = fmaxf(r0v.x + r1v.x, 0.0f);
        float hy = fmaxf(r0v.y + r1v.y, 0.0f);
        u64 h = pk2(hx, hy);

        const u64* w2r = W2c + j * 8;     // warp-uniform address -> LDCU
        #pragma unroll
        for (int p = 0; p < PP; ++p)
            acc[p] = fma2(h, w2r[p], acc[p]);
    }

    // unpack per-group activations (+final relu)
    float s0[PP], s1[PP];
    #pragma unroll
    for (int p = 0; p < PP; ++p) {
        float2 t = upk2(acc[p]);
        s0[p] = fmaxf(t.x, 0.0f);
        s1[p] = fmaxf(t.y, 0.0f);
    }

    // ---- per-group aggregation + group MLP ----
    float o0 = group_tail(s0, W3t, b3s, W4s, b4v, lane);
    if (lane == 0) out[g0 + 0] = o0;
    float o1 = group_tail(s1, W3t, b3s, W4s, b4v, lane);
    if (lane == 0) out[g0 + 1] = o1;
}

extern "C" void kernel_launch(void* const* d_in, const int* in_sizes, int n_in,
                              void* d_out, int out_size)
{
    const float* x       = (const float*)d_in[0];
    const int*   kmer    = (const int*)  d_in[1];
    const int*   indices = (const int*)  d_in[2];
    const float* emb     = (const float*)d_in[3];
    const float* W1      = (const float*)d_in[4];
    const float* b1      = (const float*)d_in[5];
    const float* W2      = (const float*)d_in[6];
    const float* b2      = (const float*)d_in[7];
    const float* W3      = (const float*)d_in[8];
    const float* b3      = (const float*)d_in[9];
    const float* W4      = (const float*)d_in[10];
    const float* b4      = (const float*)d_in[11];
    float* out = (float*)d_out;

    // Stage duplicated/packed weights into device scratch, then copy into
    // __constant__ symbols (async D2D memcpys: graph-capturable memcpy nodes).
    prep_kernel<<<12, 256>>>(W1, W2, b1, b2);

    void *p_w1 = nullptr, *p_w2 = nullptr, *p_b = nullptr;
    cudaGetSymbolAddress(&p_w1, scr_w1);
    cudaGetSymbolAddress(&p_w2, scr_w2);
    cudaGetSymbolAddress(&p_b,  scr_b);
    cudaMemcpyToSymbolAsync(W1c, p_w1, sizeof(u64) * H1 * 20, 0,
                            cudaMemcpyDeviceToDevice, 0);
    cudaMemcpyToSymbolAsync(W2c, p_w2, sizeof(u64) * H1 * 8, 0,
                            cudaMemcpyDeviceToDevice, 0);
    cudaMemcpyToSymbolAsync(bc,  p_b,  sizeof(float) * 160, 0,
                            cudaMemcpyDeviceToDevice, 0);

    cudaFuncSetAttribute(minn_fused_const_kernel,
                         cudaFuncAttributeMaxDynamicSharedMemorySize, SM_BYTES);

    // 8 warps/block * 2 groups/warp = 16 groups per block
    const int blocks = G_TOTAL / 16;   // 2048
    minn_fused_const_kernel<<<blocks, 256, SM_BYTES>>>(
        x, kmer, indices, emb, W3, b3, W4, b4, out);
}

// round 5
// speedup vs baseline: 1.7875x; 1.7875x over previous
#include <cuda_runtime.h>

#define G_TOTAL 32768
#define H1      150
#define PP      8

using u64 = unsigned long long;

// ---- packed f32x2 helpers (Blackwell sm_103a) ------------------------------
__device__ __forceinline__ u64 pk2(float a, float b) {
    u64 r;
    asm("mov.b64 %0,{%1,%2};" : "=l"(r)
        : "r"(__float_as_uint(a)), "r"(__float_as_uint(b)));
    return r;
}
__device__ __forceinline__ float2 upk2(u64 v) {
    unsigned lo, hi;
    asm("mov.b64 {%0,%1},%2;" : "=r"(lo), "=r"(hi) : "l"(v));
    return make_float2(__uint_as_float(lo), __uint_as_float(hi));
}
__device__ __forceinline__ u64 fma2(u64 a, u64 b, u64 c) {
    u64 d;
    asm("fma.rn.f32x2 %0,%1,%2,%3;" : "=l"(d) : "l"(a), "l"(b), "l"(c));
    return d;
}

// ---- shared-memory layout (float offsets) ----------------------------------
// W1n : [18][152]  natural k-major W1 rows (150 used + pad) -> LDS.64 j-pairs
// W2p : [75][8]    u64 pairs {W2[2jp][p], W2[2jp+1][p]}
// b1s : [152]      natural b1 (pad)      -> LDS.64 j-pairs
// W3t : [150][40]  transposed W3 rows (lane-distinct tail)
#define SM_W1N 0
#define SM_W2P 2736
#define SM_B1  3936
#define SM_W3T 4088
#define SM_B3  10088
#define SM_W4  10240
#define SM_B2  10392
#define SM_FLOATS 10400
#define SM_BYTES  (SM_FLOATS * 4)

// ---- per-group tail: warp stats over 32 lanes + group MLP (verified) -------
__device__ __noinline__ float group_tail(const float* a,
                                         const float* __restrict__ W3t,
                                         const float* __restrict__ b3s,
                                         const float* __restrict__ W4s,
                                         float b4v, int lane)
{
    u64 ag[20];   // packed agg pairs: ag[stat*4 + p/2] = {agg_p, agg_p+1}

    #pragma unroll
    for (int ph = 0; ph < 4; ++ph) {
        float va = a[2 * ph], vb = a[2 * ph + 1];

        // mean
        float sa = va, sb = vb;
        #pragma unroll
        for (int o = 16; o; o >>= 1) {
            sa += __shfl_xor_sync(0xffffffffu, sa, o);
            sb += __shfl_xor_sync(0xffffffffu, sb, o);
        }
        float meana = sa * (1.0f / 32.0f), meanb = sb * (1.0f / 32.0f);

        // unbiased variance (two-pass)
        float da = va - meana, db = vb - meanb;
        float qa = da * da, qb = db * db;
        #pragma unroll
        for (int o = 16; o; o >>= 1) {
            qa += __shfl_xor_sync(0xffffffffu, qa, o);
            qb += __shfl_xor_sync(0xffffffffu, qb, o);
        }
        float vara = qa * (1.0f / 31.0f), varb = qb * (1.0f / 31.0f);

        // min / max
        float mna = va, mxa = va, mnb = vb, mxb = vb;
        #pragma unroll
        for (int o = 16; o; o >>= 1) {
            mna = fminf(mna, __shfl_xor_sync(0xffffffffu, mna, o));
            mxa = fmaxf(mxa, __shfl_xor_sync(0xffffffffu, mxa, o));
            mnb = fminf(mnb, __shfl_xor_sync(0xffffffffu, mnb, o));
            mxb = fmaxf(mxb, __shfl_xor_sync(0xffffffffu, mxb, o));
        }

        // lower median via warp bitonic sort (two sorts interleaved)
        float ta = va, tb = vb;
        #pragma unroll
        for (int k = 2; k <= 32; k <<= 1) {
            #pragma unroll
            for (int j = k >> 1; j > 0; j >>= 1) {
                float oa = __shfl_xor_sync(0xffffffffu, ta, j);
                float ob = __shfl_xor_sync(0xffffffffu, tb, j);
                bool keep_lo = (((lane & j) == 0) == ((lane & k) == 0));
                float la = fminf(ta, oa), ha = fmaxf(ta, oa);
                float lb = fminf(tb, ob), hb = fmaxf(tb, ob);
                ta = keep_lo ? la : ha;
                tb = keep_lo ? lb : hb;
            }
        }
        float meda = __shfl_sync(0xffffffffu, ta, 15);
        float medb = __shfl_sync(0xffffffffu, tb, 15);

        ag[0 * 4 + ph] = pk2(meana, meanb);
        ag[1 * 4 + ph] = pk2(vara, varb);
        ag[2 * 4 + ph] = pk2(mna, mnb);
        ag[3 * 4 + ph] = pk2(meda, medb);
        ag[4 * 4 + ph] = pk2(mxa, mxb);
    }

    // group MLP: 40 -> 150 (relu) -> 1, hidden units strided over lanes
    float zp = 0.0f;
    #pragma unroll 1
    for (int j = lane; j < H1; j += 32) {
        const ulonglong2* wr = (const ulonglong2*)(W3t + j * 40);
        u64 t2a = 0ull, t2b = 0ull;
        #pragma unroll
        for (int q = 0; q < 10; ++q) {
            ulonglong2 w = wr[q];
            t2a = fma2(ag[2 * q],     w.x, t2a);
            t2b = fma2(ag[2 * q + 1], w.y, t2b);
        }
        float2 sa = upk2(t2a), sb = upk2(t2b);
        float t = (sa.x + sa.y) + (sb.x + sb.y) + b3s[j];
        t = fmaxf(t, 0.0f);
        zp = fmaf(t, W4s[j], zp);
    }
    #pragma unroll
    for (int o = 16; o; o >>= 1) zp += __shfl_xor_sync(0xffffffffu, zp, o);

    return 1.0f / (1.0f + __expf(-(zp + b4v)));
}

__global__ void __launch_bounds__(256, 2)
minn_fused_jpair_kernel(const float* __restrict__ x,
                        const int*   __restrict__ kmer,
                        const int*   __restrict__ indices,
                        const float* __restrict__ emb,
                        const float* __restrict__ W1, const float* __restrict__ b1,
                        const float* __restrict__ W2, const float* __restrict__ b2,
                        const float* __restrict__ W3, const float* __restrict__ b3,
                        const float* __restrict__ W4, const float* __restrict__ b4,
                        float* __restrict__ out)
{
    extern __shared__ float sm[];
    float* W1n  = sm + SM_W1N;
    u64*   W2pu = (u64*)(sm + SM_W2P);
    float* b1s  = sm + SM_B1;
    float* W3t  = sm + SM_W3T;
    float* b3s  = sm + SM_B3;
    float* W4s  = sm + SM_W4;
    float* b2s  = sm + SM_B2;

    const int tid = threadIdx.x;

    // ---- stage weights (natural layouts; no duplication) ----
    for (int i = tid; i < 18 * 152; i += 256) {
        int k = i / 152, j = i - k * 152;
        W1n[i] = (j < H1) ? W1[k * H1 + j] : 0.0f;
    }
    for (int i = tid; i < 75 * PP; i += 256) {
        int jp = i >> 3, p = i & 7;
        W2pu[i] = pk2(W2[(2 * jp) * PP + p], W2[(2 * jp + 1) * PP + p]);
    }
    for (int i = tid; i < 152; i += 256)
        b1s[i] = (i < H1) ? b1[i] : 0.0f;
    for (int i = tid; i < 40 * H1; i += 256) {
        int j = i / 40, k = i - j * 40;
        W3t[i] = W3[k * H1 + j];
    }
    for (int i = tid; i < H1; i += 256) {
        b3s[i] = b3[i];
        W4s[i] = W4[i];
    }
    if (tid < PP) b2s[tid] = b2[tid];
    const float b4v = __ldg(b4);
    __syncthreads();

    const int warp = tid >> 5;
    const int lane = tid & 31;
    const int g0 = (blockIdx.x * 8 + warp) * 2;   // 2 groups per warp

    // ---- gather the 2 reads this lane owns; duplicate once into f32x2 ----
    const int r0 = indices[(g0 + 0) * 32 + lane];
    const int r1 = indices[(g0 + 1) * 32 + lane];

    u64 d0[18], d1[18];   // d0[k] = {in_r0[k], in_r0[k]}, d1 likewise for r1
    {
        const float4* p0 = (const float4*)(x + (size_t)r0 * 16);
        const float4* p1 = (const float4*)(x + (size_t)r1 * 16);
        #pragma unroll
        for (int q = 0; q < 4; ++q) {
            float4 v0 = p0[q], v1 = p1[q];
            d0[4 * q + 0] = pk2(v0.x, v0.x);  d1[4 * q + 0] = pk2(v1.x, v1.x);
            d0[4 * q + 1] = pk2(v0.y, v0.y);  d1[4 * q + 1] = pk2(v1.y, v1.y);
            d0[4 * q + 2] = pk2(v0.z, v0.z);  d1[4 * q + 2] = pk2(v1.z, v1.z);
            d0[4 * q + 3] = pk2(v0.w, v0.w);  d1[4 * q + 3] = pk2(v1.w, v1.w);
        }
        float2 e0 = ((const float2*)emb)[kmer[r0]];
        float2 e1 = ((const float2*)emb)[kmer[r1]];
        d0[16] = pk2(e0.x, e0.x);  d1[16] = pk2(e1.x, e1.x);
        d0[17] = pk2(e0.y, e0.y);  d1[17] = pk2(e1.y, e1.y);
    }

    // ---- per-read MLP, hidden units processed in pairs {j, j+1} ----
    // ac*[p] = {sum over even j, sum over odd j} of h_j * W2[j][p]
    u64 ac0[PP], ac1[PP];
    #pragma unroll
    for (int p = 0; p < PP; ++p) { ac0[p] = 0ull; ac1[p] = 0ull; }

    #pragma unroll 1
    for (int jp = 0; jp < 75; ++jp) {
        u64 b1p = *(const u64*)(b1s + 2 * jp);       // LDS.64 broadcast
        u64 h0 = b1p, h1 = b1p;                      // {h_j, h_j+1} per read
        const float* w1c = W1n + 2 * jp;
        #pragma unroll
        for (int k = 0; k < 18; ++k) {
            u64 w = *(const u64*)(w1c + k * 152);    // LDS.64 broadcast, distinct
            h0 = fma2(d0[k], w, h0);
            h1 = fma2(d1[k], w, h1);
        }
        float2 u0 = upk2(h0), u1 = upk2(h1);
        h0 = pk2(fmaxf(u0.x, 0.0f), fmaxf(u0.y, 0.0f));
        h1 = pk2(fmaxf(u1.x, 0.0f), fmaxf(u1.y, 0.0f));

        const u64* w2r = W2pu + jp * PP;
        #pragma unroll
        for (int p = 0; p < PP; ++p) {
            u64 w2 = w2r[p];                          // LDS.64 broadcast
            ac0[p] = fma2(h0, w2, ac0[p]);
            ac1[p] = fma2(h1, w2, ac1[p]);
        }
    }

    // fold even/odd halves, add b2, final relu
    float s0[PP], s1[PP];
    #pragma unroll
    for (int p = 0; p < PP; ++p) {
        float bp = b2s[p];
        float2 t = upk2(ac0[p]);
        s0[p] = fmaxf(t.x + t.y + bp, 0.0f);
        float2 u = upk2(ac1[p]);
        s1[p] = fmaxf(u.x + u.y + bp, 0.0f);
    }

    // ---- per-group aggregation + group MLP ----
    float o0 = group_tail(s0, W3t, b3s, W4s, b4v, lane);
    if (lane == 0) out[g0 + 0] = o0;
    float o1 = group_tail(s1, W3t, b3s, W4s, b4v, lane);
    if (lane == 0) out[g0 + 1] = o1;
}

extern "C" void kernel_launch(void* const* d_in, const int* in_sizes, int n_in,
                              void* d_out, int out_size)
{
    const float* x       = (const float*)d_in[0];
    const int*   kmer    = (const int*)  d_in[1];
    const int*   indices = (const int*)  d_in[2];
    const float* emb     = (const float*)d_in[3];
    const float* W1      = (const float*)d_in[4];
    const float* b1      = (const float*)d_in[5];
    const float* W2      = (const float*)d_in[6];
    const float* b2      = (const float*)d_in[7];
    const float* W3      = (const float*)d_in[8];
    const float* b3      = (const float*)d_in[9];
    const float* W4      = (const float*)d_in[10];
    const float* b4      = (const float*)d_in[11];
    float* out = (float*)d_out;

    cudaFuncSetAttribute(minn_fused_jpair_kernel,
                         cudaFuncAttributeMaxDynamicSharedMemorySize, SM_BYTES);

    // 8 warps/block * 2 groups/warp = 16 groups per block
    const int blocks = G_TOTAL / 16;   // 2048
    minn_fused_jpair_kernel<<<blocks, 256, SM_BYTES>>>(
        x, kmer, indices, emb, W1, b1, W2, b2, W3, b3, W4, b4, out);
}

// round 6
// speedup vs baseline: 1.8916x; 1.0583x over previous
#include <cuda_runtime.h>

#define G_TOTAL 32768
#define H1      150
#define PP      8

using u64 = unsigned long long;

// ---- packed f32x2 helpers (Blackwell sm_103a) ------------------------------
__device__ __forceinline__ u64 pk2(float a, float b) {
    u64 r;
    asm("mov.b64 %0,{%1,%2};" : "=l"(r)
        : "r"(__float_as_uint(a)), "r"(__float_as_uint(b)));
    return r;
}
__device__ __forceinline__ float2 upk2(u64 v) {
    unsigned lo, hi;
    asm("mov.b64 {%0,%1},%2;" : "=r"(lo), "=r"(hi) : "l"(v));
    return make_float2(__uint_as_float(lo), __uint_as_float(hi));
}
__device__ __forceinline__ u64 fma2(u64 a, u64 b, u64 c) {
    u64 d;
    asm("fma.rn.f32x2 %0,%1,%2,%3;" : "=l"(d) : "l"(a), "l"(b), "l"(c));
    return d;
}
__device__ __forceinline__ u64 relu2(u64 v) {
    float2 t = upk2(v);
    return pk2(fmaxf(t.x, 0.0f), fmaxf(t.y, 0.0f));
}

// ---- shared-memory layout (float offsets) ----------------------------------
// W1n : [18][152]  natural k-major W1 rows (150 used + pad) -> LDS.64 j-pairs
// W2p : [75][8]    u64 pairs {W2[2jp][p], W2[2jp+1][p]}
// b1s : [152]
// W3t : [150][40]  transposed W3 rows (lane-distinct tail)
#define SM_W1N 0
#define SM_W2P 2736
#define SM_B1  3936
#define SM_W3T 4088
#define SM_B3  10088
#define SM_W4  10240
#define SM_B2  10392
#define SM_FLOATS 10400
#define SM_BYTES  (SM_FLOATS * 4)

// ---- per-group tail: warp stats over 32 lanes + group MLP (verified) -------
__device__ __noinline__ float group_tail(const float* a,
                                         const float* __restrict__ W3t,
                                         const float* __restrict__ b3s,
                                         const float* __restrict__ W4s,
                                         float b4v, int lane)
{
    u64 ag[20];   // packed agg pairs: ag[stat*4 + p/2] = {agg_p, agg_p+1}

    #pragma unroll
    for (int ph = 0; ph < 4; ++ph) {
        float va = a[2 * ph], vb = a[2 * ph + 1];

        // mean
        float sa = va, sb = vb;
        #pragma unroll
        for (int o = 16; o; o >>= 1) {
            sa += __shfl_xor_sync(0xffffffffu, sa, o);
            sb += __shfl_xor_sync(0xffffffffu, sb, o);
        }
        float meana = sa * (1.0f / 32.0f), meanb = sb * (1.0f / 32.0f);

        // unbiased variance (two-pass)
        float da = va - meana, db = vb - meanb;
        float qa = da * da, qb = db * db;
        #pragma unroll
        for (int o = 16; o; o >>= 1) {
            qa += __shfl_xor_sync(0xffffffffu, qa, o);
            qb += __shfl_xor_sync(0xffffffffu, qb, o);
        }
        float vara = qa * (1.0f / 31.0f), varb = qb * (1.0f / 31.0f);

        // min / max
        float mna = va, mxa = va, mnb = vb, mxb = vb;
        #pragma unroll
        for (int o = 16; o; o >>= 1) {
            mna = fminf(mna, __shfl_xor_sync(0xffffffffu, mna, o));
            mxa = fmaxf(mxa, __shfl_xor_sync(0xffffffffu, mxa, o));
            mnb = fminf(mnb, __shfl_xor_sync(0xffffffffu, mnb, o));
            mxb = fmaxf(mxb, __shfl_xor_sync(0xffffffffu, mxb, o));
        }

        // lower median via warp bitonic sort (two sorts interleaved)
        float ta = va, tb = vb;
        #pragma unroll
        for (int k = 2; k <= 32; k <<= 1) {
            #pragma unroll
            for (int j = k >> 1; j > 0; j >>= 1) {
                float oa = __shfl_xor_sync(0xffffffffu, ta, j);
                float ob = __shfl_xor_sync(0xffffffffu, tb, j);
                bool keep_lo = (((lane & j) == 0) == ((lane & k) == 0));
                float la = fminf(ta, oa), ha = fmaxf(ta, oa);
                float lb = fminf(tb, ob), hb = fmaxf(tb, ob);
                ta = keep_lo ? la : ha;
                tb = keep_lo ? lb : hb;
            }
        }
        float meda = __shfl_sync(0xffffffffu, ta, 15);
        float medb = __shfl_sync(0xffffffffu, tb, 15);

        ag[0 * 4 + ph] = pk2(meana, meanb);
        ag[1 * 4 + ph] = pk2(vara, varb);
        ag[2 * 4 + ph] = pk2(mna, mnb);
        ag[3 * 4 + ph] = pk2(meda, medb);
        ag[4 * 4 + ph] = pk2(mxa, mxb);
    }

    // group MLP: 40 -> 150 (relu) -> 1, hidden units strided over lanes
    float zp = 0.0f;
    #pragma unroll 1
    for (int j = lane; j < H1; j += 32) {
        const ulonglong2* wr = (const ulonglong2*)(W3t + j * 40);
        u64 t2a = 0ull, t2b = 0ull;
        #pragma unroll
        for (int q = 0; q < 10; ++q) {
            ulonglong2 w = wr[q];
            t2a = fma2(ag[2 * q],     w.x, t2a);
            t2b = fma2(ag[2 * q + 1], w.y, t2b);
        }
        float2 sa = upk2(t2a), sb = upk2(t2b);
        float t = (sa.x + sa.y) + (sb.x + sb.y) + b3s[j];
        t = fmaxf(t, 0.0f);
        zp = fmaf(t, W4s[j], zp);
    }
    #pragma unroll
    for (int o = 16; o; o >>= 1) zp += __shfl_xor_sync(0xffffffffu, zp, o);

    return 1.0f / (1.0f + __expf(-(zp + b4v)));
}

__global__ void __launch_bounds__(128, 3)
minn_fused_diag_kernel(const float* __restrict__ x,
                       const int*   __restrict__ kmer,
                       const int*   __restrict__ indices,
                       const float* __restrict__ emb,
                       const float* __restrict__ W1, const float* __restrict__ b1,
                       const float* __restrict__ W2, const float* __restrict__ b2,
                       const float* __restrict__ W3, const float* __restrict__ b3,
                       const float* __restrict__ W4, const float* __restrict__ b4,
                       float* __restrict__ out)
{
    extern __shared__ float sm[];
    float* W1n  = sm + SM_W1N;
    u64*   W2pu = (u64*)(sm + SM_W2P);
    float* b1s  = sm + SM_B1;
    float* W3t  = sm + SM_W3T;
    float* b3s  = sm + SM_B3;
    float* W4s  = sm + SM_W4;
    float* b2s  = sm + SM_B2;

    const int tid = threadIdx.x;

    // ---- stage weights (natural layouts; no duplication anywhere) ----
    for (int i = tid; i < 18 * 152; i += 128) {
        int k = i / 152, j = i - k * 152;
        W1n[i] = (j < H1) ? W1[k * H1 + j] : 0.0f;
    }
    for (int i = tid; i < 75 * PP; i += 128) {
        int jp = i >> 3, p = i & 7;
        W2pu[i] = pk2(W2[(2 * jp) * PP + p], W2[(2 * jp + 1) * PP + p]);
    }
    for (int i = tid; i < 152; i += 128)
        b1s[i] = (i < H1) ? b1[i] : 0.0f;
    for (int i = tid; i < 40 * H1; i += 128) {
        int j = i / 40, k = i - j * 40;
        W3t[i] = W3[k * H1 + j];
    }
    for (int i = tid; i < H1; i += 128) {
        b3s[i] = b3[i];
        W4s[i] = W4[i];
    }
    if (tid < PP) b2s[tid] = b2[tid];
    const float b4v = __ldg(b4);
    __syncthreads();

    const int warp = tid >> 5;
    const int lane = tid & 31;
    const int g0 = (blockIdx.x * 4 + warp) * 4;   // 4 groups per warp

    // ---- gather the 4 reads this lane owns, packed read-pair-wise ----
    const int r0 = indices[(g0 + 0) * 32 + lane];
    const int r1 = indices[(g0 + 1) * 32 + lane];
    const int r2 = indices[(g0 + 2) * 32 + lane];
    const int r3 = indices[(g0 + 3) * 32 + lane];

    u64 rp0[18], rp1[18];   // rp0[k]={r0[k],r1[k]}, rp1[k]={r2[k],r3[k]}
    {
        const float4* p0 = (const float4*)(x + (size_t)r0 * 16);
        const float4* p1 = (const float4*)(x + (size_t)r1 * 16);
        const float4* p2 = (const float4*)(x + (size_t)r2 * 16);
        const float4* p3 = (const float4*)(x + (size_t)r3 * 16);
        #pragma unroll
        for (int q = 0; q < 4; ++q) {
            float4 v0 = p0[q], v1 = p1[q], v2 = p2[q], v3 = p3[q];
            rp0[4 * q + 0] = pk2(v0.x, v1.x);  rp1[4 * q + 0] = pk2(v2.x, v3.x);
            rp0[4 * q + 1] = pk2(v0.y, v1.y);  rp1[4 * q + 1] = pk2(v2.y, v3.y);
            rp0[4 * q + 2] = pk2(v0.z, v1.z);  rp1[4 * q + 2] = pk2(v2.z, v3.z);
            rp0[4 * q + 3] = pk2(v0.w, v1.w);  rp1[4 * q + 3] = pk2(v2.w, v3.w);
        }
        float2 e0 = ((const float2*)emb)[kmer[r0]];
        float2 e1 = ((const float2*)emb)[kmer[r1]];
        float2 e2 = ((const float2*)emb)[kmer[r2]];
        float2 e3 = ((const float2*)emb)[kmer[r3]];
        rp0[16] = pk2(e0.x, e1.x);  rp1[16] = pk2(e2.x, e3.x);
        rp0[17] = pk2(e0.y, e1.y);  rp1[17] = pk2(e2.y, e3.y);
    }

    // ---- per-read MLP via diagonal f32x2 accumulation ----
    // A00 = {h_j(r0), h_j+1(r1)}, A01 = {h_j+1(r0), h_j(r1)} (likewise A1x for r2,r3)
    // ACC0[p] = {acc(r0,p), acc(r1,p)}, ACC1[p] = {acc(r2,p), acc(r3,p)}
    u64 ACC0[PP], ACC1[PP];
    #pragma unroll
    for (int p = 0; p < PP; ++p) { ACC0[p] = 0ull; ACC1[p] = 0ull; }

    #pragma unroll 1
    for (int jp = 0; jp < 75; ++jp) {
        float2 bf = *(const float2*)(b1s + 2 * jp);    // LDS.64 {bj, bj+1}
        u64 Bp = pk2(bf.x, bf.y);
        u64 Bs = pk2(bf.y, bf.x);
        u64 A00 = Bp, A01 = Bs, A10 = Bp, A11 = Bs;

        const float* w1c = W1n + 2 * jp;
        #pragma unroll
        for (int k = 0; k < 18; ++k) {
            float2 wf = *(const float2*)(w1c + k * 152);  // LDS.64, distinct pair
            u64 wp = pk2(wf.x, wf.y);
            u64 ws = pk2(wf.y, wf.x);                     // swapped copy
            A00 = fma2(rp0[k], wp, A00);
            A01 = fma2(rp0[k], ws, A01);
            A10 = fma2(rp1[k], wp, A10);
            A11 = fma2(rp1[k], ws, A11);
        }
        A00 = relu2(A00);  A01 = relu2(A01);
        A10 = relu2(A10);  A11 = relu2(A11);

        const u64* w2r = W2pu + jp * PP;
        #pragma unroll
        for (int p = 0; p < PP; ++p) {
            float2 w2f = upk2(w2r[p]);                    // LDS.64 {w2j, w2j+1}
            u64 w2p_ = pk2(w2f.x, w2f.y);
            u64 w2s_ = pk2(w2f.y, w2f.x);
            ACC0[p] = fma2(A00, w2p_, ACC0[p]);
            ACC0[p] = fma2(A01, w2s_, ACC0[p]);
            ACC1[p] = fma2(A10, w2p_, ACC1[p]);
            ACC1[p] = fma2(A11, w2s_, ACC1[p]);
        }
    }

    // add b2, final relu, unpack per-group activations
    float s0[PP], s1[PP], s2[PP], s3[PP];
    #pragma unroll
    for (int p = 0; p < PP; ++p) {
        float bp = b2s[p];
        float2 t = upk2(ACC0[p]);
        s0[p] = fmaxf(t.x + bp, 0.0f);
        s1[p] = fmaxf(t.y + bp, 0.0f);
        float2 u = upk2(ACC1[p]);
        s2[p] = fmaxf(u.x + bp, 0.0f);
        s3[p] = fmaxf(u.y + bp, 0.0f);
    }

    // ---- per-group aggregation + group MLP ----
    float o0 = group_tail(s0, W3t, b3s, W4s, b4v, lane);
    if (lane == 0) out[g0 + 0] = o0;
    float o1 = group_tail(s1, W3t, b3s, W4s, b4v, lane);
    if (lane == 0) out[g0 + 1] = o1;
    float o2 = group_tail(s2, W3t, b3s, W4s, b4v, lane);
    if (lane == 0) out[g0 + 2] = o2;
    float o3 = group_tail(s3, W3t, b3s, W4s, b4v, lane);
    if (lane == 0) out[g0 + 3] = o3;
}

extern "C" void kernel_launch(void* const* d_in, const int* in_sizes, int n_in,
                              void* d_out, int out_size)
{
    const float* x       = (const float*)d_in[0];
    const int*   kmer    = (const int*)  d_in[1];
    const int*   indices = (const int*)  d_in[2];
    const float* emb     = (const float*)d_in[3];
    const float* W1      = (const float*)d_in[4];
    const float* b1      = (const float*)d_in[5];
    const float* W2      = (const float*)d_in[6];
    const float* b2      = (const float*)d_in[7];
    const float* W3      = (const float*)d_in[8];
    const float* b3      = (const float*)d_in[9];
    const float* W4      = (const float*)d_in[10];
    const float* b4      = (const float*)d_in[11];
    float* out = (float*)d_out;

    cudaFuncSetAttribute(minn_fused_diag_kernel,
                         cudaFuncAttributeMaxDynamicSharedMemorySize, SM_BYTES);

    // 4 warps/block * 4 groups/warp = 16 groups per block
    const int blocks = G_TOTAL / 16;   // 2048
    minn_fused_diag_kernel<<<blocks, 128, SM_BYTES>>>(
        x, kmer, indices, emb, W1, b1, W2, b2, W3, b3, W4, b4, out);
}

// round 7
// speedup vs baseline: 2.0796x; 1.0994x over previous
#include <cuda_runtime.h>

#define G_TOTAL 32768
#define H1      150
#define PP      8

using u64 = unsigned long long;

// ---- packed f32x2 helpers (Blackwell sm_103a) ------------------------------
__device__ __forceinline__ u64 pk2(float a, float b) {
    u64 r;
    asm("mov.b64 %0,{%1,%2};" : "=l"(r)
        : "r"(__float_as_uint(a)), "r"(__float_as_uint(b)));
    return r;
}
__device__ __forceinline__ float2 upk2(u64 v) {
    unsigned lo, hi;
    asm("mov.b64 {%0,%1},%2;" : "=r"(lo), "=r"(hi) : "l"(v));
    return make_float2(__uint_as_float(lo), __uint_as_float(hi));
}
__device__ __forceinline__ u64 fma2(u64 a, u64 b, u64 c) {
    u64 d;
    asm("fma.rn.f32x2 %0,%1,%2,%3;" : "=l"(d) : "l"(a), "l"(b), "l"(c));
    return d;
}
__device__ __forceinline__ u64 relu2(u64 v) {
    float2 t = upk2(v);
    return pk2(fmaxf(t.x, 0.0f), fmaxf(t.y, 0.0f));
}

// ---- shared-memory layout (float offsets) ----------------------------------
// H padded 150 -> 152 (zero weights; exact: relu(0)=0 and W2 pad rows are 0)
// W1n : [18][152]  natural k-major W1 rows -> LDS.128 j-quads
// W2p : [76][8]    u64 pairs {W2[2jp][p], W2[2jp+1][p]} (pad jp=75 zero)
// b1s : [152]
// W3t : [150][40]  transposed W3 rows (lane-distinct tail)
#define SM_W1N 0
#define SM_W2P 2736
#define SM_B1  3952
#define SM_W3T 4104
#define SM_B3  10104
#define SM_W4  10256
#define SM_B2  10408
#define SM_FLOATS 10416
#define SM_BYTES  (SM_FLOATS * 4)

// ---- per-group tail: warp stats over 32 lanes + group MLP (verified) -------
__device__ __noinline__ float group_tail(const float* a,
                                         const float* __restrict__ W3t,
                                         const float* __restrict__ b3s,
                                         const float* __restrict__ W4s,
                                         float b4v, int lane)
{
    u64 ag[20];   // packed agg pairs: ag[stat*4 + p/2] = {agg_p, agg_p+1}

    #pragma unroll
    for (int ph = 0; ph < 4; ++ph) {
        float va = a[2 * ph], vb = a[2 * ph + 1];

        // mean
        float sa = va, sb = vb;
        #pragma unroll
        for (int o = 16; o; o >>= 1) {
            sa += __shfl_xor_sync(0xffffffffu, sa, o);
            sb += __shfl_xor_sync(0xffffffffu, sb, o);
        }
        float meana = sa * (1.0f / 32.0f), meanb = sb * (1.0f / 32.0f);

        // unbiased variance (two-pass)
        float da = va - meana, db = vb - meanb;
        float qa = da * da, qb = db * db;
        #pragma unroll
        for (int o = 16; o; o >>= 1) {
            qa += __shfl_xor_sync(0xffffffffu, qa, o);
            qb += __shfl_xor_sync(0xffffffffu, qb, o);
        }
        float vara = qa * (1.0f / 31.0f), varb = qb * (1.0f / 31.0f);

        // min / max
        float mna = va, mxa = va, mnb = vb, mxb = vb;
        #pragma unroll
        for (int o = 16; o; o >>= 1) {
            mna = fminf(mna, __shfl_xor_sync(0xffffffffu, mna, o));
            mxa = fmaxf(mxa, __shfl_xor_sync(0xffffffffu, mxa, o));
            mnb = fminf(mnb, __shfl_xor_sync(0xffffffffu, mnb, o));
            mxb = fmaxf(mxb, __shfl_xor_sync(0xffffffffu, mxb, o));
        }

        // lower median via warp bitonic sort (two sorts interleaved)
        float ta = va, tb = vb;
        #pragma unroll
        for (int k = 2; k <= 32; k <<= 1) {
            #pragma unroll
            for (int j = k >> 1; j > 0; j >>= 1) {
                float oa = __shfl_xor_sync(0xffffffffu, ta, j);
                float ob = __shfl_xor_sync(0xffffffffu, tb, j);
                bool keep_lo = (((lane & j) == 0) == ((lane & k) == 0));
                float la = fminf(ta, oa), ha = fmaxf(ta, oa);
                float lb = fminf(tb, ob), hb = fmaxf(tb, ob);
                ta = keep_lo ? la : ha;
                tb = keep_lo ? lb : hb;
            }
        }
        float meda = __shfl_sync(0xffffffffu, ta, 15);
        float medb = __shfl_sync(0xffffffffu, tb, 15);

        ag[0 * 4 + ph] = pk2(meana, meanb);
        ag[1 * 4 + ph] = pk2(vara, varb);
        ag[2 * 4 + ph] = pk2(mna, mnb);
        ag[3 * 4 + ph] = pk2(meda, medb);
        ag[4 * 4 + ph] = pk2(mxa, mxb);
    }

    // group MLP: 40 -> 150 (relu) -> 1, hidden units strided over lanes
    float zp = 0.0f;
    #pragma unroll 1
    for (int j = lane; j < H1; j += 32) {
        const ulonglong2* wr = (const ulonglong2*)(W3t + j * 40);
        u64 t2a = 0ull, t2b = 0ull;
        #pragma unroll
        for (int q = 0; q < 10; ++q) {
            ulonglong2 w = wr[q];
            t2a = fma2(ag[2 * q],     w.x, t2a);
            t2b = fma2(ag[2 * q + 1], w.y, t2b);
        }
        float2 sa = upk2(t2a), sb = upk2(t2b);
        float t = (sa.x + sa.y) + (sb.x + sb.y) + b3s[j];
        t = fmaxf(t, 0.0f);
        zp = fmaf(t, W4s[j], zp);
    }
    #pragma unroll
    for (int o = 16; o; o >>= 1) zp += __shfl_xor_sync(0xffffffffu, zp, o);

    return 1.0f / (1.0f + __expf(-(zp + b4v)));
}

__global__ void __launch_bounds__(128, 3)
minn_fused_diag2_kernel(const float* __restrict__ x,
                        const int*   __restrict__ kmer,
                        const int*   __restrict__ indices,
                        const float* __restrict__ emb,
                        const float* __restrict__ W1, const float* __restrict__ b1,
                        const float* __restrict__ W2, const float* __restrict__ b2,
                        const float* __restrict__ W3, const float* __restrict__ b3,
                        const float* __restrict__ W4, const float* __restrict__ b4,
                        float* __restrict__ out)
{
    extern __shared__ float sm[];
    float* W1n  = sm + SM_W1N;
    u64*   W2pu = (u64*)(sm + SM_W2P);
    float* b1s  = sm + SM_B1;
    float* W3t  = sm + SM_W3T;
    float* b3s  = sm + SM_B3;
    float* W4s  = sm + SM_W4;
    float* b2s  = sm + SM_B2;

    const int tid = threadIdx.x;

    // ---- stage weights (natural layouts; no duplication anywhere) ----
    for (int i = tid; i < 18 * 152; i += 128) {
        int k = i / 152, j = i - k * 152;
        W1n[i] = (j < H1) ? W1[k * H1 + j] : 0.0f;
    }
    for (int i = tid; i < 76 * PP; i += 128) {
        int jp = i >> 3, p = i & 7;
        int j0 = 2 * jp, j1 = 2 * jp + 1;
        float w0 = (j0 < H1) ? W2[j0 * PP + p] : 0.0f;
        float w1 = (j1 < H1) ? W2[j1 * PP + p] : 0.0f;
        W2pu[i] = pk2(w0, w1);
    }
    for (int i = tid; i < 152; i += 128)
        b1s[i] = (i < H1) ? b1[i] : 0.0f;
    for (int i = tid; i < 40 * H1; i += 128) {
        int j = i / 40, k = i - j * 40;
        W3t[i] = W3[k * H1 + j];
    }
    for (int i = tid; i < H1; i += 128) {
        b3s[i] = b3[i];
        W4s[i] = W4[i];
    }
    if (tid < PP) b2s[tid] = b2[tid];
    const float b4v = __ldg(b4);
    __syncthreads();

    const int warp = tid >> 5;
    const int lane = tid & 31;
    const int g0 = (blockIdx.x * 4 + warp) * 4;   // 4 groups per warp

    // ---- gather the 4 reads this lane owns, packed read-pair-wise ----
    const int r0 = indices[(g0 + 0) * 32 + lane];
    const int r1 = indices[(g0 + 1) * 32 + lane];
    const int r2 = indices[(g0 + 2) * 32 + lane];
    const int r3 = indices[(g0 + 3) * 32 + lane];

    u64 rp0[18], rp1[18];   // rp0[k]={r0[k],r1[k]}, rp1[k]={r2[k],r3[k]}
    {
        const float4* p0 = (const float4*)(x + (size_t)r0 * 16);
        const float4* p1 = (const float4*)(x + (size_t)r1 * 16);
        const float4* p2 = (const float4*)(x + (size_t)r2 * 16);
        const float4* p3 = (const float4*)(x + (size_t)r3 * 16);
        #pragma unroll
        for (int q = 0; q < 4; ++q) {
            float4 v0 = p0[q], v1 = p1[q], v2 = p2[q], v3 = p3[q];
            rp0[4 * q + 0] = pk2(v0.x, v1.x);  rp1[4 * q + 0] = pk2(v2.x, v3.x);
            rp0[4 * q + 1] = pk2(v0.y, v1.y);  rp1[4 * q + 1] = pk2(v2.y, v3.y);
            rp0[4 * q + 2] = pk2(v0.z, v1.z);  rp1[4 * q + 2] = pk2(v2.z, v3.z);
            rp0[4 * q + 3] = pk2(v0.w, v1.w);  rp1[4 * q + 3] = pk2(v2.w, v3.w);
        }
        float2 e0 = ((const float2*)emb)[kmer[r0]];
        float2 e1 = ((const float2*)emb)[kmer[r1]];
        float2 e2 = ((const float2*)emb)[kmer[r2]];
        float2 e3 = ((const float2*)emb)[kmer[r3]];
        rp0[16] = pk2(e0.x, e1.x);  rp1[16] = pk2(e2.x, e3.x);
        rp0[17] = pk2(e0.y, e1.y);  rp1[17] = pk2(e2.y, e3.y);
    }

    // ---- per-read MLP via diagonal f32x2, two j-pairs per iteration ----
    // A** = j-pair {2jp2*2, +1};  C** = j-pair {2jp2*2+2, +3}
    u64 ACC0[PP], ACC1[PP];
    #pragma unroll
    for (int p = 0; p < PP; ++p) { ACC0[p] = 0ull; ACC1[p] = 0ull; }

    #pragma unroll 1
    for (int jp2 = 0; jp2 < 38; ++jp2) {
        float4 bq = *(const float4*)(b1s + 4 * jp2);      // LDS.128
        u64 BpA = pk2(bq.x, bq.y), BsA = pk2(bq.y, bq.x);
        u64 BpB = pk2(bq.z, bq.w), BsB = pk2(bq.w, bq.z);
        u64 A00 = BpA, A01 = BsA, A10 = BpA, A11 = BsA;
        u64 C00 = BpB, C01 = BsB, C10 = BpB, C11 = BsB;

        const float* w1c = W1n + 4 * jp2;
        #pragma unroll
        for (int k = 0; k < 18; ++k) {
            float4 wq = *(const float4*)(w1c + k * 152);  // LDS.128: 4 j's
            u64 wpA = pk2(wq.x, wq.y), wsA = pk2(wq.y, wq.x);
            u64 wpB = pk2(wq.z, wq.w), wsB = pk2(wq.w, wq.z);
            A00 = fma2(rp0[k], wpA, A00);
            A01 = fma2(rp0[k], wsA, A01);
            A10 = fma2(rp1[k], wpA, A10);
            A11 = fma2(rp1[k], wsA, A11);
            C00 = fma2(rp0[k], wpB, C00);
            C01 = fma2(rp0[k], wsB, C01);
            C10 = fma2(rp1[k], wpB, C10);
            C11 = fma2(rp1[k], wsB, C11);
        }
        A00 = relu2(A00);  A01 = relu2(A01);
        A10 = relu2(A10);  A11 = relu2(A11);
        C00 = relu2(C00);  C01 = relu2(C01);
        C10 = relu2(C10);  C11 = relu2(C11);

        const ulonglong2* w2a = (const ulonglong2*)(W2pu + (2 * jp2) * PP);
        const ulonglong2* w2b = (const ulonglong2*)(W2pu + (2 * jp2 + 1) * PP);
        #pragma unroll
        for (int q = 0; q < 4; ++q) {
            ulonglong2 wa = w2a[q];    // LDS.128: {p=2q, p=2q+1} of j-pair A
            ulonglong2 wb = w2b[q];    // same for j-pair B
            float2 wa0 = upk2(wa.x), wa1 = upk2(wa.y);
            float2 wb0 = upk2(wb.x), wb1 = upk2(wb.y);
            u64 wap0 = pk2(wa0.x, wa0.y), was0 = pk2(wa0.y, wa0.x);
            u64 wap1 = pk2(wa1.x, wa1.y), was1 = pk2(wa1.y, wa1.x);
            u64 wbp0 = pk2(wb0.x, wb0.y), wbs0 = pk2(wb0.y, wb0.x);
            u64 wbp1 = pk2(wb1.x, wb1.y), wbs1 = pk2(wb1.y, wb1.x);

            ACC0[2 * q]     = fma2(A00, wap0, ACC0[2 * q]);
            ACC0[2 * q]     = fma2(A01, was0, ACC0[2 * q]);
            ACC0[2 * q]     = fma2(C00, wbp0, ACC0[2 * q]);
            ACC0[2 * q]     = fma2(C01, wbs0, ACC0[2 * q]);
            ACC0[2 * q + 1] = fma2(A00, wap1, ACC0[2 * q + 1]);
            ACC0[2 * q + 1] = fma2(A01, was1, ACC0[2 * q + 1]);
            ACC0[2 * q + 1] = fma2(C00, wbp1, ACC0[2 * q + 1]);
            ACC0[2 * q + 1] = fma2(C01, wbs1, ACC0[2 * q + 1]);

            ACC1[2 * q]     = fma2(A10, wap0, ACC1[2 * q]);
            ACC1[2 * q]     = fma2(A11, was0, ACC1[2 * q]);
            ACC1[2 * q]     = fma2(C10, wbp0, ACC1[2 * q]);
            ACC1[2 * q]     = fma2(C11, wbs0, ACC1[2 * q]);
            ACC1[2 * q + 1] = fma2(A10, wap1, ACC1[2 * q + 1]);
            ACC1[2 * q + 1] = fma2(A11, was1, ACC1[2 * q + 1]);
            ACC1[2 * q + 1] = fma2(C10, wbp1, ACC1[2 * q + 1]);
            ACC1[2 * q + 1] = fma2(C11, wbs1, ACC1[2 * q + 1]);
        }
    }

    // add b2, final relu, unpack per-group activations
    float s0[PP], s1[PP], s2[PP], s3[PP];
    #pragma unroll
    for (int p = 0; p < PP; ++p) {
        float bp = b2s[p];
        float2 t = upk2(ACC0[p]);
        s0[p] = fmaxf(t.x + bp, 0.0f);
        s1[p] = fmaxf(t.y + bp, 0.0f);
        float2 u = upk2(ACC1[p]);
        s2[p] = fmaxf(u.x + bp, 0.0f);
        s3[p] = fmaxf(u.y + bp, 0.0f);
    }

    // ---- per-group aggregation + group MLP ----
    float o0 = group_tail(s0, W3t, b3s, W4s, b4v, lane);
    if (lane == 0) out[g0 + 0] = o0;
    float o1 = group_tail(s1, W3t, b3s, W4s, b4v, lane);
    if (lane == 0) out[g0 + 1] = o1;
    float o2 = group_tail(s2, W3t, b3s, W4s, b4v, lane);
    if (lane == 0) out[g0 + 2] = o2;
    float o3 = group_tail(s3, W3t, b3s, W4s, b4v, lane);
    if (lane == 0) out[g0 + 3] = o3;
}

extern "C" void kernel_launch(void* const* d_in, const int* in_sizes, int n_in,
                              void* d_out, int out_size)
{
    const float* x       = (const float*)d_in[0];
    const int*   kmer    = (const int*)  d_in[1];
    const int*   indices = (const int*)  d_in[2];
    const float* emb     = (const float*)d_in[3];
    const float* W1      = (const float*)d_in[4];
    const float* b1      = (const float*)d_in[5];
    const float* W2      = (const float*)d_in[6];
    const float* b2      = (const float*)d_in[7];
    const float* W3      = (const float*)d_in[8];
    const float* b3      = (const float*)d_in[9];
    const float* W4      = (const float*)d_in[10];
    const float* b4      = (const float*)d_in[11];
    float* out = (float*)d_out;

    cudaFuncSetAttribute(minn_fused_diag2_kernel,
                         cudaFuncAttributeMaxDynamicSharedMemorySize, SM_BYTES);

    // 4 warps/block * 4 groups/warp = 16 groups per block
    const int blocks = G_TOTAL / 16;   // 2048
    minn_fused_diag2_kernel<<<blocks, 128, SM_BYTES>>>(
        x, kmer, indices, emb, W1, b1, W2, b2, W3, b3, W4, b4, out);
}